// round 16
// baseline (speedup 1.0000x reference)
#include <cuda_runtime.h>
#include <cstdint>

// GaussianRP: x (8,16,32,1024) f32, log_sigma scalar f32
// out (8,16,1024,1024) f32:
//   rp[b,c,t,s] = exp(-max(|x_t|^2+|x_s|^2-2<x_t,x_s>, 0) / (2 sigma^2))
//
// Round 16: R15 champion (3xTF32 mma.sync, 64x64 tile, 128 thr/4 warps,
// warp=32x32, pre-packed fragments, pair-fastest grid) with:
//  - B column remap s = 32*(c&1) + 8*(c>>1) + nb  (c = MMA instr column):
//    each thread's 4 nbl outputs become s-contiguous -> normal-tile store
//    is 8x STG.128 (one 128B line per row per instr) instead of 16x STG.64
//    scattered. Normal-store wavefronts halved, no shuffles.
//  - B hi/lo fragments interleaved in one uint4 array: 16 LDG.128 replaces
//    32 LDG.64 (fewer issue slots + address ALU).

#define NDIM  32
#define NT    1024
#define NBC   128

#define TILE  64
#define NTILE (NT / TILE)                  // 16
#define NPAIR (NTILE * (NTILE + 1) / 2)    // 136

#define TWORDS 2048                        // A fragment words per (bc,tile)
#define FR_TOT (NBC * NTILE * TWORDS)      // 4,194,304
#define BWORDS 4096                        // interleaved B words per (bc,tile)
#define NORM_N (NBC * NT)                  // 131072

__device__ float g_sqnorm[NBC * NT];
__device__ float g_scale;   // 1/(2 sigma^2)

__device__ float g_Ahi[FR_TOT];
__device__ float g_Alo[FR_TOT];
__device__ float g_Bil[2 * FR_TOT];        // {bh.x,bh.y,bl.x,bl.y} per (nb,kk,lane)

__device__ __forceinline__ uint32_t f2tf32(float v) {
    uint32_t r;
    asm("cvt.rna.tf32.f32 %0, %1;" : "=r"(r) : "f"(v));
    return r;
}

// Combined prologue: A-frag pack | B-frag pack (interleaved, col-remapped) |
// sqnorms (+g_scale).
__global__ __launch_bounds__(256)
void prologue_kernel(const float* __restrict__ x,
                     const float* __restrict__ log_sigma) {
    int idx = blockIdx.x * blockDim.x + threadIdx.x;
    if (idx < FR_TOT) {
        // A: same layout as champion
        int w    = idx;
        int idxA = w & 3;
        int lane = (w >> 2) & 31;
        int ks   = (w >> 7) & 3;
        int ms   = (w >> 9) & 3;
        int tile = (w >> 11) & 15;
        int bc   = w >> 15;
        int tl   = ms * 16 + ((idxA >> 1) & 1) * 8 + (lane >> 2);
        int k    = ks * 8 + (idxA & 1) * 4 + (lane & 3);
        float v  = x[(size_t)bc * NDIM * NT + k * NT + tile * TILE + tl];
        float hf = __uint_as_float(f2tf32(v));
        g_Ahi[w] = hf;
        g_Alo[w] = __uint_as_float(f2tf32(v - hf));
    } else if (idx < 2 * FR_TOT) {
        // B: one thread per (idxB,lane,ks,nb,tile,bc); writes hi and lo words.
        int w    = idx - FR_TOT;
        int idxB = w & 1;
        int lane = (w >> 1) & 31;
        int ks   = (w >> 6) & 3;
        int nb   = (w >> 8) & 7;
        int tile = (w >> 11) & 15;
        int bc   = w >> 15;
        int n    = lane >> 2;                       // MMA instruction column
        // column remap: s = 32*(n&1) + 8*(n>>1) + nb
        int sl   = 32 * (n & 1) + 8 * (n >> 1) + nb;
        int k    = ks * 8 + idxB * 4 + (lane & 3);
        float v  = x[(size_t)bc * NDIM * NT + k * NT + tile * TILE + sl];
        float hf = __uint_as_float(f2tf32(v));
        size_t base = (size_t)(bc * NTILE + tile) * BWORDS
                    + ((nb * 4 + ks) * 32 + lane) * 4;
        g_Bil[base + idxB]     = hf;                           // hi word
        g_Bil[base + idxB + 2] = __uint_as_float(f2tf32(v - hf)); // lo word
    } else if (idx < 2 * FR_TOT + NORM_N) {
        int n = idx - 2 * FR_TOT;
        if (n == 0) g_scale = 0.5f * __expf(-2.f * log_sigma[0]);
        int bc = n >> 10;
        int t  = n & (NT - 1);
        const float* p = x + (size_t)bc * NDIM * NT + t;
        float s = 0.f;
#pragma unroll
        for (int d = 0; d < NDIM; ++d) {
            float v = p[d * NT];
            s = fmaf(v, v, s);
        }
        g_sqnorm[n] = s;
    }
}

__device__ __forceinline__ void mma_tf32(float d[4],
                                         uint32_t a0, uint32_t a1,
                                         uint32_t a2, uint32_t a3,
                                         uint32_t b0, uint32_t b1) {
    asm volatile(
        "mma.sync.aligned.m16n8k8.row.col.f32.tf32.tf32.f32 "
        "{%0,%1,%2,%3}, {%4,%5,%6,%7}, {%8,%9}, {%0,%1,%2,%3};"
        : "+f"(d[0]), "+f"(d[1]), "+f"(d[2]), "+f"(d[3])
        : "r"(a0), "r"(a1), "r"(a2), "r"(a3), "r"(b0), "r"(b1));
}

__global__ __launch_bounds__(128, 5)
void gaussian_rp_mma(float* __restrict__ out) {
    const int p  = blockIdx.x;        // pair fastest -> L2 locality per bc
    const int bc = blockIdx.y;

    int ss = 0;
#pragma unroll
    for (int c = 1; c < NTILE; ++c)
        ss += (p >= c * (c + 1) / 2) ? 1 : 0;
    const int ts = p - ss * (ss + 1) / 2;
    const int t0 = ts * TILE;
    const int s0 = ss * TILE;

    const int tid  = threadIdx.x;
    const int lane = tid & 31;
    const int wid  = tid >> 5;        // 0..3
    const int wm   = wid & 1;          // t half (32 rows)
    const int wn   = wid >> 1;         // s half (4 nb-blocks)
    const int g    = lane >> 2;
    const int tig  = lane & 3;

    const uint32_t* __restrict__ Ahi =
        (const uint32_t*)g_Ahi + (size_t)(bc * NTILE + ts) * TWORDS;
    const uint32_t* __restrict__ Alo =
        (const uint32_t*)g_Alo + (size_t)(bc * NTILE + ts) * TWORDS;
    const uint32_t* __restrict__ Bil =
        (const uint32_t*)g_Bil + (size_t)(bc * NTILE + ss) * BWORDS;

    // warp tile: 32(t) x 32(s-cols, remapped) = 2 msi x 4 nbl
    float acc[2][4][4];
#pragma unroll
    for (int i = 0; i < 2; ++i)
#pragma unroll
        for (int j = 0; j < 4; ++j)
#pragma unroll
            for (int q = 0; q < 4; ++q) acc[i][j][q] = 0.f;

#pragma unroll
    for (int kk = 0; kk < 4; ++kk) {
        uint4 fh[2], fl[2];
#pragma unroll
        for (int msi = 0; msi < 2; ++msi) {
            int off = (((wm * 2 + msi) * 4 + kk) * 32 + lane) * 4;
            fh[msi] = *(const uint4*)(Ahi + off);
            fl[msi] = *(const uint4*)(Alo + off);
        }
#pragma unroll
        for (int nbl = 0; nbl < 4; ++nbl) {
            int nbg = wn * 4 + nbl;
            uint4 bq = *(const uint4*)(Bil + ((nbg * 4 + kk) * 32 + lane) * 4);
            // bq = {bh0, bh1, bl0, bl1}
#pragma unroll
            for (int msi = 0; msi < 2; ++msi) {
                // stored order [a0,a2,a1,a3] -> operands (a0,a1,a2,a3)
                mma_tf32(acc[msi][nbl], fh[msi].x, fh[msi].z, fh[msi].y, fh[msi].w, bq.x, bq.y); // hi*hi
                mma_tf32(acc[msi][nbl], fl[msi].x, fl[msi].z, fl[msi].y, fl[msi].w, bq.x, bq.y); // lo*hi
                mma_tf32(acc[msi][nbl], fh[msi].x, fh[msi].z, fh[msi].y, fh[msi].w, bq.z, bq.w); // hi*lo
            }
        }
    }

    // ---- epilogue: d2 -> exp -> dual store ----
    // col map: d0/d2 (e=0) -> s = 8*tig + 4*wn + nbl
    //          d1/d3 (e=1) -> s = 32 + 8*tig + 4*wn + nbl
    const float scale  = g_scale;
    const float scale2 = 2.f * scale;
    const float* sq = &g_sqnorm[bc * NT];

    float snt[2][2];
#pragma unroll
    for (int msi = 0; msi < 2; ++msi) {
        int tl = wm * 32 + msi * 16 + g;
        snt[msi][0] = scale * sq[t0 + tl];
        snt[msi][1] = scale * sq[t0 + tl + 8];
    }
    const int sbase = 8 * tig + 4 * wn;    // local s for e=0, nbl=0
    float4 q0 = *(const float4*)&sq[s0 + sbase];
    float4 q1 = *(const float4*)&sq[s0 + 32 + sbase];
    float sns0[4] = { scale * q0.x, scale * q0.y, scale * q0.z, scale * q0.w };
    float sns1[4] = { scale * q1.x, scale * q1.y, scale * q1.z, scale * q1.w };

    float* ob = out + (size_t)bc * NT * NT;
    const bool offdiag = (ts != ss);

#pragma unroll
    for (int msi = 0; msi < 2; ++msi) {
        int tl = wm * 32 + msi * 16 + g;
        float rA0[4], rA1[4], rB0[4], rB1[4];  // [row tl e0/e1, row tl+8 e0/e1]
#pragma unroll
        for (int nbl = 0; nbl < 4; ++nbl) {
            float* d = acc[msi][nbl];
            rA0[nbl] = __expf(fminf(fmaf(scale2, d[0], -(snt[msi][0] + sns0[nbl])), 0.f));
            rA1[nbl] = __expf(fminf(fmaf(scale2, d[1], -(snt[msi][0] + sns1[nbl])), 0.f));
            rB0[nbl] = __expf(fminf(fmaf(scale2, d[2], -(snt[msi][1] + sns0[nbl])), 0.f));
            rB1[nbl] = __expf(fminf(fmaf(scale2, d[3], -(snt[msi][1] + sns1[nbl])), 0.f));
        }

        // normal tile: 4x STG.128, each row's quad lands in one 128B line
        float* row0 = ob + (size_t)(t0 + tl) * NT + s0;
        float* row1 = ob + (size_t)(t0 + tl + 8) * NT + s0;
        *(float4*)(row0 + sbase)      = make_float4(rA0[0], rA0[1], rA0[2], rA0[3]);
        *(float4*)(row0 + 32 + sbase) = make_float4(rA1[0], rA1[1], rA1[2], rA1[3]);
        *(float4*)(row1 + sbase)      = make_float4(rB0[0], rB0[1], rB0[2], rB0[3]);
        *(float4*)(row1 + 32 + sbase) = make_float4(rB1[0], rB1[1], rB1[2], rB1[3]);

        // transposed tile: scalar (t-values per thread have stride 8)
        if (offdiag) {
#pragma unroll
            for (int nbl = 0; nbl < 4; ++nbl) {
                size_t c0 = (size_t)(s0 + sbase + nbl) * NT + t0;
                size_t c1 = (size_t)(s0 + 32 + sbase + nbl) * NT + t0;
                ob[c0 + tl]     = rA0[nbl];
                ob[c1 + tl]     = rA1[nbl];
                ob[c0 + tl + 8] = rB0[nbl];
                ob[c1 + tl + 8] = rB1[nbl];
            }
        }
    }
}

extern "C" void kernel_launch(void* const* d_in, const int* in_sizes, int n_in,
                              void* d_out, int out_size) {
    const float* x  = (const float*)d_in[0];
    const float* ls = (const float*)d_in[1];
    float* out      = (float*)d_out;

    int prologue_threads = 2 * FR_TOT + NORM_N;
    prologue_kernel<<<(prologue_threads + 255) / 256, 256>>>(x, ls);

    dim3 grid(NPAIR, NBC);
    gaussian_rp_mma<<<grid, 128>>>(out);
}